// round 8
// baseline (speedup 1.0000x reference)
#include <cuda_runtime.h>
#include <cuda_bf16.h>
#include <cstdint>

#define NB     32
#define NPTS   2048
#define TPB    256
#define NWARP  (TPB / 32)
#define RTILES 4
#define ROWS   (NPTS / RTILES)          // 512 rows per block
#define CPP    4                        // col-pairs per thread (4 * 256 * 2 = 2048 cols)
#define BIGSQ  1.0e16f

// Packed f32x2 ops (sm_103a — PTX-only)
#define FMA_F32X2(d, a, b, c) \
    asm("fma.rn.f32x2 %0, %1, %2, %3;" : "=l"(d) : "l"(a), "l"(b), "l"(c))
#define ADD_F32X2(d, a, b) \
    asm("add.rn.f32x2 %0, %1, %2;" : "=l"(d) : "l"(a), "l"(b))

__device__ __forceinline__ unsigned long long pack2(float lo, float hi) {
    unsigned long long r;
    asm("mov.b64 %0, {%1, %2};" : "=l"(r) : "f"(lo), "f"(hi));
    return r;
}
__device__ __forceinline__ void unpack2(float& lo, float& hi, unsigned long long v) {
    asm("mov.b64 {%0, %1}, %2;" : "=f"(lo), "=f"(hi) : "l"(v));
}

// per-block col-min partials: [batch][row-tile][col]
__device__ float g_colmin[NB * RTILES * NPTS];

__global__ void chamfer_zero_kernel(float* out) {
    if (threadIdx.x < NB) out[threadIdx.x] = 0.0f;
}

// Kernel B: rows = outputs, cols = targets. Computes each pair ONCE.
// Row-side sum (0.5 * sum min1) accumulated here; col-min partials to scratch.
__global__ __launch_bounds__(TPB) void chamfer_main_kernel(
    const int*   __restrict__ o_w,   const float* __restrict__ o_pts,
    const int*   __restrict__ t_w,   const float* __restrict__ t_pts,
    float*       __restrict__ out)
{
    const int b    = blockIdx.x;
    const int tile = blockIdx.y;
    const int tid  = threadIdx.x;
    const int wid  = tid >> 5;
    const int lane = tid & 31;
    const int row0 = tile * ROWS;

    // rows staged broadcast-packed: sA[r] = {(m2x,m2x),(m2y,m2y)}, sB[r] = {(m2z,m2z),(r2,r2)}
    __shared__ ulonglong2 sA[ROWS + 1];
    __shared__ ulonglong2 sB[ROWS + 1];
    __shared__ float rowpart[NWARP][ROWS];   // per-warp row-min partials

    // ---- stage rows ----
    #pragma unroll
    for (int k = 0; k < ROWS / TPB; k++) {
        int r = tid + k * TPB;
        int n = row0 + r;
        const float* p = o_pts + ((size_t)b * NPTS + n) * 3;
        int w = o_w[b * NPTS + n];
        float x = p[0], y = p[1], z = p[2];
        float r2 = x * x + y * y + z * z;
        float mx = -2.0f * x, my = -2.0f * y, mz = -2.0f * z;
        if (!w) { mx = 0.f; my = 0.f; mz = 0.f; r2 = BIGSQ; }  // masked row loses col-mins
        ulonglong2 va, vb;
        va.x = pack2(mx, mx);  va.y = pack2(my, my);
        vb.x = pack2(mz, mz);  vb.y = pack2(r2, r2);
        sA[r] = va;  sB[r] = vb;
    }
    if (tid == 0) {
        sA[ROWS] = make_ulonglong2(0ull, 0ull);
        sB[ROWS] = make_ulonglong2(0ull, 0ull);
    }

    // ---- thread-owned columns (4 packed pairs = 8 cols) ----
    unsigned long long X[CPP], Y[CPP], Z[CPP], C2[CPP];
    float cmlo[CPP], cmhi[CPP];
    #pragma unroll
    for (int p = 0; p < CPP; p++) {
        int j  = tid + p * TPB;              // col-pair index 0..1023
        int c0 = 2 * j;
        const float* q = t_pts + ((size_t)b * NPTS + c0) * 3;
        int w0 = t_w[b * NPTS + c0];
        int w1 = t_w[b * NPTS + c0 + 1];
        float x0 = q[0], y0 = q[1], z0 = q[2];
        float x1 = q[3], y1 = q[4], z1 = q[5];
        if (!w0) { x0 = 0.f; y0 = 0.f; z0 = 0.f; }
        if (!w1) { x1 = 0.f; y1 = 0.f; z1 = 0.f; }
        float c0s = w0 ? (x0*x0 + y0*y0 + z0*z0) : BIGSQ;   // masked col loses row-mins
        float c1s = w1 ? (x1*x1 + y1*y1 + z1*z1) : BIGSQ;
        X[p]  = pack2(x0, x1);
        Y[p]  = pack2(y0, y1);
        Z[p]  = pack2(z0, z1);
        C2[p] = pack2(c0s, c1s);
        cmlo[p] = 3.4e38f;  cmhi[p] = 3.4e38f;
    }

    __syncthreads();

    // ---- stream rows: per row = 2 LDS.128 + 4*(ADD2 + 3 FFMA2 + 4 FMNMX) + butterfly ----
    ulonglong2 nA = sA[0], nB = sB[0];
    #pragma unroll 4
    for (int r = 0; r < ROWS; r++) {
        ulonglong2 va = nA, vb = nB;
        nA = sA[r + 1];  nB = sB[r + 1];
        float rclo = 3.4e38f, rchi = 3.4e38f;
        #pragma unroll
        for (int p = 0; p < CPP; p++) {
            unsigned long long v;
            ADD_F32X2(v, C2[p], vb.y);          // c^2 + r^2
            FMA_F32X2(v, va.x, X[p], v);        // - 2 x_r x_c
            FMA_F32X2(v, va.y, Y[p], v);
            FMA_F32X2(v, vb.x, Z[p], v);
            float v0, v1;
            unpack2(v0, v1, v);
            cmlo[p] = fminf(cmlo[p], v0);       // col mins (lane-local)
            cmhi[p] = fminf(cmhi[p], v1);
            rclo = fminf(rclo, v0);             // row candidate
            rchi = fminf(rchi, v1);
        }
        float rc = fminf(rclo, rchi);
        #pragma unroll
        for (int m = 16; m > 0; m >>= 1)
            rc = fminf(rc, __shfl_xor_sync(0xffffffffu, rc, m));
        if (lane == 0) rowpart[wid][r] = rc;    // warp's row-min over its 256 cols
    }

    // ---- col-min partials to global scratch ----
    float* cm = g_colmin + ((size_t)b * RTILES + tile) * NPTS;
    #pragma unroll
    for (int p = 0; p < CPP; p++) {
        int c0 = 2 * (tid + p * TPB);
        cm[c0]     = cmlo[p];
        cm[c0 + 1] = cmhi[p];
    }

    __syncthreads();

    // ---- row-side finish: combine warp partials, clamp, mask, sum ----
    float acc = 0.0f;
    #pragma unroll
    for (int k = 0; k < ROWS / TPB; k++) {
        int r = tid + k * TPB;
        float mn = rowpart[0][r];
        #pragma unroll
        for (int w = 1; w < NWARP; w++) mn = fminf(mn, rowpart[w][r]);
        float wr = (float)o_w[b * NPTS + row0 + r];
        acc += fmaxf(mn, 0.0f) * wr;
    }

    __shared__ float red[NWARP];
    #pragma unroll
    for (int o = 16; o > 0; o >>= 1)
        acc += __shfl_down_sync(0xffffffffu, acc, o);
    if (lane == 0) red[wid] = acc;
    __syncthreads();
    if (tid < NWARP) {
        acc = red[tid];
        #pragma unroll
        for (int o = NWARP / 2; o > 0; o >>= 1)
            acc += __shfl_down_sync((1u << NWARP) - 1u, acc, o);
        if (tid == 0) atomicAdd(&out[b], 0.5f * acc);
    }
}

// Kernel C: reduce col-min partials over row-tiles, clamp, mask, sum.
__global__ __launch_bounds__(TPB) void chamfer_col_kernel(
    const int* __restrict__ t_w, float* __restrict__ out)
{
    const int b   = blockIdx.x;
    const int tid = threadIdx.x;
    const float* cmb = g_colmin + (size_t)b * RTILES * NPTS;

    float acc = 0.0f;
    #pragma unroll
    for (int k = 0; k < NPTS / TPB; k++) {
        int c = tid + k * TPB;
        float mn = cmb[c];
        #pragma unroll
        for (int t = 1; t < RTILES; t++) mn = fminf(mn, cmb[t * NPTS + c]);
        float wc = (float)t_w[b * NPTS + c];
        acc += fmaxf(mn, 0.0f) * wc;
    }

    __shared__ float red[NWARP];
    const int wid = tid >> 5, lane = tid & 31;
    #pragma unroll
    for (int o = 16; o > 0; o >>= 1)
        acc += __shfl_down_sync(0xffffffffu, acc, o);
    if (lane == 0) red[wid] = acc;
    __syncthreads();
    if (tid < NWARP) {
        acc = red[tid];
        #pragma unroll
        for (int o = NWARP / 2; o > 0; o >>= 1)
            acc += __shfl_down_sync((1u << NWARP) - 1u, acc, o);
        if (tid == 0) atomicAdd(&out[b], 0.5f * acc);
    }
}

extern "C" void kernel_launch(void* const* d_in, const int* in_sizes, int n_in,
                              void* d_out, int out_size) {
    const int*   o_w   = (const int*)  d_in[0];
    const float* o_pts = (const float*)d_in[1];
    const int*   t_w   = (const int*)  d_in[2];
    const float* t_pts = (const float*)d_in[3];
    float* out = (float*)d_out;

    chamfer_zero_kernel<<<1, 32>>>(out);
    dim3 grid(NB, RTILES);                       // 128 blocks
    chamfer_main_kernel<<<grid, TPB>>>(o_w, o_pts, t_w, t_pts, out);
    chamfer_col_kernel<<<NB, TPB>>>(t_w, out);
}

// round 10
// speedup vs baseline: 1.1340x; 1.1340x over previous
#include <cuda_runtime.h>
#include <cuda_bf16.h>
#include <cstdint>

#define NB     32
#define NPTS   2048
#define TPB    128
#define NWARP  (TPB / 32)
#define RTILES 8
#define ROWS   (NPTS / RTILES)          // 256 rows per block
#define CPP    8                        // packed col-pairs per thread (16 cols)
#define BIGSQ  1.0e16f

// Packed f32x2 ops (sm_103a — PTX-only)
#define FMA_F32X2(d, a, b, c) \
    asm("fma.rn.f32x2 %0, %1, %2, %3;" : "=l"(d) : "l"(a), "l"(b), "l"(c))
#define ADD_F32X2(d, a, b) \
    asm("add.rn.f32x2 %0, %1, %2;" : "=l"(d) : "l"(a), "l"(b))

__device__ __forceinline__ unsigned long long pack2(float lo, float hi) {
    unsigned long long r;
    asm("mov.b64 %0, {%1, %2};" : "=l"(r) : "f"(lo), "f"(hi));
    return r;
}
__device__ __forceinline__ void unpack2(float& lo, float& hi, unsigned long long v) {
    asm("mov.b64 {%0, %1}, %2;" : "=f"(lo), "=f"(hi) : "l"(v));
}

// scratch: col-min partials [b][tile][col], row-sums [b][tile]
__device__ float g_colmin[NB * RTILES * NPTS];
__device__ float g_rowsum[NB * RTILES];

// Main: rows = outputs (streamed from shared), cols = targets (register-owned).
// Every pair computed exactly ONCE, feeding both row-min and col-min.
__global__ __launch_bounds__(TPB) void chamfer_main_kernel(
    const int*   __restrict__ o_w,   const float* __restrict__ o_pts,
    const int*   __restrict__ t_w,   const float* __restrict__ t_pts)
{
    const int b    = blockIdx.x;
    const int tile = blockIdx.y;
    const int tid  = threadIdx.x;
    const int wid  = tid >> 5;
    const int lane = tid & 31;
    const int row0 = tile * ROWS;

    __shared__ ulonglong2 sA[ROWS];          // (m2x,m2x | m2y,m2y)
    __shared__ ulonglong2 sB[ROWS];          // (m2z,m2z | r2,r2)
    __shared__ float rowpart[NWARP][ROWS];   // per-warp row mins (each warp covers ALL cols of its lane set? no — all 2048 cols? see below)

    // ---- stage rows: 2 rows per thread ----
    #pragma unroll
    for (int k = 0; k < ROWS / TPB; k++) {
        int r = tid + k * TPB;
        int n = row0 + r;
        const float* p = o_pts + ((size_t)b * NPTS + n) * 3;
        int w = o_w[b * NPTS + n];
        float x = p[0], y = p[1], z = p[2];
        float r2 = x * x + y * y + z * z;
        float mx = -2.0f * x, my = -2.0f * y, mz = -2.0f * z;
        if (!w) { mx = 0.f; my = 0.f; mz = 0.f; r2 = BIGSQ; }  // masked row can't win col-mins
        ulonglong2 va, vb;
        va.x = pack2(mx, mx);  va.y = pack2(my, my);
        vb.x = pack2(mz, mz);  vb.y = pack2(r2, r2);
        sA[r] = va;  sB[r] = vb;
    }

    // ---- thread-owned columns: 8 packed pairs = 16 cols ----
    unsigned long long X[CPP], Y[CPP], Z[CPP], C2[CPP];
    float cmlo[CPP], cmhi[CPP];
    #pragma unroll
    for (int p = 0; p < CPP; p++) {
        int j  = tid + p * TPB;              // pair index 0..1023
        int c0 = 2 * j;
        const float* q = t_pts + ((size_t)b * NPTS + c0) * 3;
        int w0 = t_w[b * NPTS + c0];
        int w1 = t_w[b * NPTS + c0 + 1];
        float x0 = q[0], y0 = q[1], z0 = q[2];
        float x1 = q[3], y1 = q[4], z1 = q[5];
        if (!w0) { x0 = 0.f; y0 = 0.f; z0 = 0.f; }
        if (!w1) { x1 = 0.f; y1 = 0.f; z1 = 0.f; }
        float c0s = w0 ? (x0*x0 + y0*y0 + z0*z0) : BIGSQ;  // masked col can't win row-mins
        float c1s = w1 ? (x1*x1 + y1*y1 + z1*z1) : BIGSQ;
        X[p]  = pack2(x0, x1);
        Y[p]  = pack2(y0, y1);
        Z[p]  = pack2(z0, z1);
        C2[p] = pack2(c0s, c1s);
        cmlo[p] = 3.4e38f;  cmhi[p] = 3.4e38f;
    }

    __syncthreads();

    // ---- stream rows: per warp-row = 2 LDS + 8*(ADD2+3FFMA2+2FMNMX+2fmin) + 5-shfl butterfly ----
    #pragma unroll 2
    for (int r = 0; r < ROWS; r++) {
        const ulonglong2 va = sA[r];
        const ulonglong2 vb = sB[r];
        float rc = 3.4e38f;
        #pragma unroll
        for (int p = 0; p < CPP; p++) {
            unsigned long long v;
            ADD_F32X2(v, C2[p], vb.y);          // c^2 + r^2
            FMA_F32X2(v, va.x, X[p], v);        // - 2 x_r x_c
            FMA_F32X2(v, va.y, Y[p], v);
            FMA_F32X2(v, vb.x, Z[p], v);
            float v0, v1;
            unpack2(v0, v1, v);
            cmlo[p] = fminf(cmlo[p], v0);       // col mins (lane-local)
            cmhi[p] = fminf(cmhi[p], v1);
            rc = fminf(rc, fminf(v0, v1));      // row candidate (this lane's 16 cols)
        }
        #pragma unroll
        for (int m = 16; m > 0; m >>= 1)
            rc = fminf(rc, __shfl_xor_sync(0xffffffffu, rc, m));
        if (lane == 0) rowpart[wid][r] = rc;    // warp's min over its 512 cols
    }

    // ---- col-min partials -> global scratch (unique (b,tile,col) per thread) ----
    float* cm = g_colmin + ((size_t)b * RTILES + tile) * NPTS;
    #pragma unroll
    for (int p = 0; p < CPP; p++) {
        int c0 = 2 * (tid + p * TPB);
        cm[c0]     = cmlo[p];
        cm[c0 + 1] = cmhi[p];
    }

    __syncthreads();

    // ---- row-side finish: merge warp partials, clamp, mask, sum over tile ----
    float acc = 0.0f;
    #pragma unroll
    for (int k = 0; k < ROWS / TPB; k++) {
        int r = tid + k * TPB;
        float mn = rowpart[0][r];
        #pragma unroll
        for (int w = 1; w < NWARP; w++) mn = fminf(mn, rowpart[w][r]);
        float wr = (float)o_w[b * NPTS + row0 + r];
        acc += fmaxf(mn, 0.0f) * wr;
    }

    __shared__ float red[NWARP];
    #pragma unroll
    for (int o = 16; o > 0; o >>= 1)
        acc += __shfl_down_sync(0xffffffffu, acc, o);
    if (lane == 0) red[wid] = acc;
    __syncthreads();
    if (tid < NWARP) {
        acc = red[tid];
        #pragma unroll
        for (int o = NWARP / 2; o > 0; o >>= 1)
            acc += __shfl_down_sync((1u << NWARP) - 1u, acc, o);
        if (tid == 0) g_rowsum[b * RTILES + tile] = acc;
    }
}

// Finish: reduce col-min partials over tiles + combine with row sums.
__global__ __launch_bounds__(256) void chamfer_finish_kernel(
    const int* __restrict__ t_w, float* __restrict__ out)
{
    const int b   = blockIdx.x;
    const int tid = threadIdx.x;
    const float* cmb = g_colmin + (size_t)b * RTILES * NPTS;

    float acc = 0.0f;
    #pragma unroll
    for (int k = 0; k < NPTS / 256; k++) {
        int c = tid + k * 256;
        float mn = cmb[c];
        #pragma unroll
        for (int t = 1; t < RTILES; t++) mn = fminf(mn, cmb[t * NPTS + c]);
        float wc = (float)t_w[b * NPTS + c];
        acc += fmaxf(mn, 0.0f) * wc;
    }

    __shared__ float red[8];
    const int wid = tid >> 5, lane = tid & 31;
    #pragma unroll
    for (int o = 16; o > 0; o >>= 1)
        acc += __shfl_down_sync(0xffffffffu, acc, o);
    if (lane == 0) red[wid] = acc;
    __syncthreads();
    if (tid < 8) {
        acc = red[tid];
        #pragma unroll
        for (int o = 4; o > 0; o >>= 1)
            acc += __shfl_down_sync(0xffu, acc, o);
        if (tid == 0) {
            float rs = 0.0f;
            #pragma unroll
            for (int t = 0; t < RTILES; t++) rs += g_rowsum[b * RTILES + t];
            out[b] = 0.5f * (rs + acc);
        }
    }
}

extern "C" void kernel_launch(void* const* d_in, const int* in_sizes, int n_in,
                              void* d_out, int out_size) {
    const int*   o_w   = (const int*)  d_in[0];
    const float* o_pts = (const float*)d_in[1];
    const int*   t_w   = (const int*)  d_in[2];
    const float* t_pts = (const float*)d_in[3];
    float* out = (float*)d_out;

    dim3 grid(NB, RTILES);                       // 256 blocks
    chamfer_main_kernel<<<grid, TPB>>>(o_w, o_pts, t_w, t_pts);
    chamfer_finish_kernel<<<NB, 256>>>(t_w, out);
}

// round 11
// speedup vs baseline: 1.3205x; 1.1645x over previous
#include <cuda_runtime.h>
#include <cuda_bf16.h>
#include <cstdint>

#define NB     32
#define NPTS   2048
#define TPB    256
#define NWARP  (TPB / 32)
#define RTILES 8
#define ROWS   (NPTS / RTILES)          // 256 rows per block
#define CPP    4                        // packed col-pairs per thread (8 cols)
#define BIGSQ  1.0e16f

// Packed f32x2 ops (sm_103a — PTX-only)
#define FMA_F32X2(d, a, b, c) \
    asm("fma.rn.f32x2 %0, %1, %2, %3;" : "=l"(d) : "l"(a), "l"(b), "l"(c))
#define ADD_F32X2(d, a, b) \
    asm("add.rn.f32x2 %0, %1, %2;" : "=l"(d) : "l"(a), "l"(b))

__device__ __forceinline__ unsigned long long pack2(float lo, float hi) {
    unsigned long long r;
    asm("mov.b64 %0, {%1, %2};" : "=l"(r) : "f"(lo), "f"(hi));
    return r;
}
__device__ __forceinline__ void unpack2(float& lo, float& hi, unsigned long long v) {
    asm("mov.b64 {%0, %1}, %2;" : "=f"(lo), "=f"(hi) : "l"(v));
}

// scratch: col-min partials [b][tile][col], row-sums [b][tile], arrival tickets
__device__ float g_colmin[NB * RTILES * NPTS];
__device__ float g_rowsum[NB * RTILES];
__device__ int   g_ticket[NB];          // zero-init; reset by consumer each launch

__global__ __launch_bounds__(TPB) void chamfer_kernel(
    const int*   __restrict__ o_w,   const float* __restrict__ o_pts,
    const int*   __restrict__ t_w,   const float* __restrict__ t_pts,
    float*       __restrict__ out)
{
    const int b    = blockIdx.x;
    const int tile = blockIdx.y;
    const int tid  = threadIdx.x;
    const int wid  = tid >> 5;
    const int lane = tid & 31;
    const int row0 = tile * ROWS;

    __shared__ ulonglong2 sA[ROWS];          // (m2x,m2x | m2y,m2y)
    __shared__ ulonglong2 sB[ROWS];          // (m2z,m2z | r2,r2)
    __shared__ float rowpart[NWARP][ROWS];   // per-warp row mins
    __shared__ int   s_last;

    // ---- stage rows: 1 row per thread ----
    {
        int n = row0 + tid;
        const float* p = o_pts + ((size_t)b * NPTS + n) * 3;
        int w = o_w[b * NPTS + n];
        float x = p[0], y = p[1], z = p[2];
        float r2 = x * x + y * y + z * z;
        float mx = -2.0f * x, my = -2.0f * y, mz = -2.0f * z;
        if (!w) { mx = 0.f; my = 0.f; mz = 0.f; r2 = BIGSQ; }  // masked row can't win col-mins
        ulonglong2 va, vb;
        va.x = pack2(mx, mx);  va.y = pack2(my, my);
        vb.x = pack2(mz, mz);  vb.y = pack2(r2, r2);
        sA[tid] = va;  sB[tid] = vb;
    }

    // ---- thread-owned columns: 4 packed pairs = 8 cols ----
    unsigned long long X[CPP], Y[CPP], Z[CPP], C2[CPP];
    float cmlo[CPP], cmhi[CPP];
    #pragma unroll
    for (int p = 0; p < CPP; p++) {
        int j  = tid + p * TPB;
        int c0 = 2 * j;
        const float* q = t_pts + ((size_t)b * NPTS + c0) * 3;
        int w0 = t_w[b * NPTS + c0];
        int w1 = t_w[b * NPTS + c0 + 1];
        float x0 = q[0], y0 = q[1], z0 = q[2];
        float x1 = q[3], y1 = q[4], z1 = q[5];
        if (!w0) { x0 = 0.f; y0 = 0.f; z0 = 0.f; }
        if (!w1) { x1 = 0.f; y1 = 0.f; z1 = 0.f; }
        float c0s = w0 ? (x0*x0 + y0*y0 + z0*z0) : BIGSQ;  // masked col can't win row-mins
        float c1s = w1 ? (x1*x1 + y1*y1 + z1*z1) : BIGSQ;
        X[p]  = pack2(x0, x1);
        Y[p]  = pack2(y0, y1);
        Z[p]  = pack2(z0, z1);
        C2[p] = pack2(c0s, c1s);
        cmlo[p] = 3.4e38f;  cmhi[p] = 3.4e38f;
    }

    __syncthreads();

    // ---- stream rows: per row = 2 LDS + 4*(ADD2+3FFMA2+3fmin) + tree + 5 SHFL ----
    #pragma unroll 2
    for (int r = 0; r < ROWS; r++) {
        const ulonglong2 va = sA[r];
        const ulonglong2 vb = sB[r];
        float pm[CPP];
        #pragma unroll
        for (int p = 0; p < CPP; p++) {
            unsigned long long v;
            ADD_F32X2(v, C2[p], vb.y);          // c^2 + r^2
            FMA_F32X2(v, va.x, X[p], v);        // - 2 x_r x_c
            FMA_F32X2(v, va.y, Y[p], v);
            FMA_F32X2(v, vb.x, Z[p], v);
            float v0, v1;
            unpack2(v0, v1, v);
            cmlo[p] = fminf(cmlo[p], v0);       // col mins (lane-local)
            cmhi[p] = fminf(cmhi[p], v1);
            pm[p]   = fminf(v0, v1);
        }
        float rc = fminf(fminf(pm[0], pm[1]), fminf(pm[2], pm[3]));  // tree
        #pragma unroll
        for (int m = 16; m > 0; m >>= 1)
            rc = fminf(rc, __shfl_xor_sync(0xffffffffu, rc, m));
        if (lane == 0) rowpart[wid][r] = rc;    // warp's min over its 256 cols
    }

    // ---- col-min partials -> global scratch ----
    float* cm = g_colmin + ((size_t)b * RTILES + tile) * NPTS;
    #pragma unroll
    for (int p = 0; p < CPP; p++) {
        int c0 = 2 * (tid + p * TPB);
        cm[c0]     = cmlo[p];
        cm[c0 + 1] = cmhi[p];
    }

    __syncthreads();

    // ---- row-side finish: merge warp partials, clamp, mask, sum over tile ----
    {
        float mn = rowpart[0][tid];
        #pragma unroll
        for (int w = 1; w < NWARP; w++) mn = fminf(mn, rowpart[w][tid]);
        float wr  = (float)o_w[b * NPTS + row0 + tid];
        float acc = fmaxf(mn, 0.0f) * wr;

        __shared__ float red[NWARP];
        #pragma unroll
        for (int o = 16; o > 0; o >>= 1)
            acc += __shfl_down_sync(0xffffffffu, acc, o);
        if (lane == 0) red[wid] = acc;
        __syncthreads();
        if (tid == 0) {
            float rs = 0.0f;
            #pragma unroll
            for (int w = 0; w < NWARP; w++) rs += red[w];
            g_rowsum[b * RTILES + tile] = rs;
        }
    }

    // ---- decoupled last-block reduction for this batch ----
    __threadfence();                     // every thread: publish its colmin/rowsum writes
    __syncthreads();
    if (tid == 0) s_last = atomicAdd(&g_ticket[b], 1);
    __syncthreads();
    if (s_last != RTILES - 1) return;

    __threadfence();                     // acquire side
    const float* cmb = g_colmin + (size_t)b * RTILES * NPTS;
    float acc = 0.0f;
    #pragma unroll
    for (int k = 0; k < NPTS / TPB; k++) {
        int c = tid + k * TPB;
        float mn = cmb[c];
        #pragma unroll
        for (int t = 1; t < RTILES; t++) mn = fminf(mn, cmb[t * NPTS + c]);
        float wc = (float)t_w[b * NPTS + c];
        acc += fmaxf(mn, 0.0f) * wc;
    }

    __shared__ float red2[NWARP];
    #pragma unroll
    for (int o = 16; o > 0; o >>= 1)
        acc += __shfl_down_sync(0xffffffffu, acc, o);
    if (lane == 0) red2[wid] = acc;
    __syncthreads();
    if (tid == 0) {
        float s = 0.0f;
        #pragma unroll
        for (int w = 0; w < NWARP; w++) s += red2[w];
        float rs = 0.0f;
        #pragma unroll
        for (int t = 0; t < RTILES; t++) rs += g_rowsum[b * RTILES + t];
        out[b] = 0.5f * (rs + s);
        g_ticket[b] = 0;                 // reset for next graph replay
    }
}

extern "C" void kernel_launch(void* const* d_in, const int* in_sizes, int n_in,
                              void* d_out, int out_size) {
    const int*   o_w   = (const int*)  d_in[0];
    const float* o_pts = (const float*)d_in[1];
    const int*   t_w   = (const int*)  d_in[2];
    const float* t_pts = (const float*)d_in[3];
    float* out = (float*)d_out;

    dim3 grid(NB, RTILES);                       // 256 blocks, single launch
    chamfer_kernel<<<grid, TPB>>>(o_w, o_pts, t_w, t_pts, out);
}

// round 12
// speedup vs baseline: 1.6975x; 1.2855x over previous
#include <cuda_runtime.h>
#include <cuda_bf16.h>
#include <cstdint>

#define NB     32
#define NPTS   2048
#define TPB    256
#define NWARP  (TPB / 32)
#define RTILES 8
#define ROWS   (NPTS / RTILES)          // 256 rows per block
#define CPP    4                        // packed col-pairs per thread (8 cols)
#define CHUNK  32                       // rows per transpose-reduce chunk
#define BIGSQ  1.0e16f

// Packed f32x2 ops (sm_103a — PTX-only)
#define FMA_F32X2(d, a, b, c) \
    asm("fma.rn.f32x2 %0, %1, %2, %3;" : "=l"(d) : "l"(a), "l"(b), "l"(c))
#define ADD_F32X2(d, a, b) \
    asm("add.rn.f32x2 %0, %1, %2;" : "=l"(d) : "l"(a), "l"(b))

__device__ __forceinline__ unsigned long long pack2(float lo, float hi) {
    unsigned long long r;
    asm("mov.b64 %0, {%1, %2};" : "=l"(r) : "f"(lo), "f"(hi));
    return r;
}
__device__ __forceinline__ void unpack2(float& lo, float& hi, unsigned long long v) {
    asm("mov.b64 {%0, %1}, %2;" : "=f"(lo), "=f"(hi) : "l"(v));
}

// scratch: col-min partials [b][tile][col], row-sums [b][tile], tickets
__device__ float g_colmin[NB * RTILES * NPTS];
__device__ float g_rowsum[NB * RTILES];
__device__ int   g_ticket[NB];          // zero-init; reset by consumer each launch

__global__ __launch_bounds__(TPB) void chamfer_kernel(
    const int*   __restrict__ o_w,   const float* __restrict__ o_pts,
    const int*   __restrict__ t_w,   const float* __restrict__ t_pts,
    float*       __restrict__ out)
{
    const int b    = blockIdx.x;
    const int tile = blockIdx.y;
    const int tid  = threadIdx.x;
    const int wid  = tid >> 5;
    const int lane = tid & 31;
    const int row0 = tile * ROWS;

    __shared__ ulonglong2 sA[ROWS];               // (m2x,m2x | m2y,m2y)
    __shared__ ulonglong2 sB[ROWS];               // (m2z,m2z | r2,r2)
    __shared__ float sPM[NWARP][CHUNK][33];       // per-warp row candidates (padded)
    __shared__ float rowpart[NWARP][ROWS];        // per-warp row mins
    __shared__ int   s_last;

    // ---- stage rows: 1 row per thread ----
    {
        int n = row0 + tid;
        const float* p = o_pts + ((size_t)b * NPTS + n) * 3;
        int w = o_w[b * NPTS + n];
        float x = p[0], y = p[1], z = p[2];
        float r2 = x * x + y * y + z * z;
        float mx = -2.0f * x, my = -2.0f * y, mz = -2.0f * z;
        if (!w) { mx = 0.f; my = 0.f; mz = 0.f; r2 = BIGSQ; }  // masked row can't win col-mins
        ulonglong2 va, vb;
        va.x = pack2(mx, mx);  va.y = pack2(my, my);
        vb.x = pack2(mz, mz);  vb.y = pack2(r2, r2);
        sA[tid] = va;  sB[tid] = vb;
    }

    // ---- thread-owned columns: 4 packed pairs = 8 cols ----
    unsigned long long X[CPP], Y[CPP], Z[CPP], C2[CPP];
    float cmlo[CPP], cmhi[CPP];
    #pragma unroll
    for (int p = 0; p < CPP; p++) {
        int j  = tid + p * TPB;
        int c0 = 2 * j;
        const float* q = t_pts + ((size_t)b * NPTS + c0) * 3;
        int w0 = t_w[b * NPTS + c0];
        int w1 = t_w[b * NPTS + c0 + 1];
        float x0 = q[0], y0 = q[1], z0 = q[2];
        float x1 = q[3], y1 = q[4], z1 = q[5];
        if (!w0) { x0 = 0.f; y0 = 0.f; z0 = 0.f; }
        if (!w1) { x1 = 0.f; y1 = 0.f; z1 = 0.f; }
        float c0s = w0 ? (x0*x0 + y0*y0 + z0*z0) : BIGSQ;  // masked col can't win row-mins
        float c1s = w1 ? (x1*x1 + y1*y1 + z1*z1) : BIGSQ;
        X[p]  = pack2(x0, x1);
        Y[p]  = pack2(y0, y1);
        Z[p]  = pack2(z0, z1);
        C2[p] = pack2(c0s, c1s);
        cmlo[p] = 3.4e38f;  cmhi[p] = 3.4e38f;
    }

    __syncthreads();

    // ---- stream rows in chunks of 32; no per-row shuffles ----
    for (int chunk = 0; chunk < ROWS / CHUNK; chunk++) {
        #pragma unroll 4
        for (int rr = 0; rr < CHUNK; rr++) {
            const int r = chunk * CHUNK + rr;
            const ulonglong2 va = sA[r];
            const ulonglong2 vb = sB[r];
            float pm[CPP];
            #pragma unroll
            for (int p = 0; p < CPP; p++) {
                unsigned long long v;
                ADD_F32X2(v, C2[p], vb.y);          // c^2 + r^2
                FMA_F32X2(v, va.x, X[p], v);        // - 2 x_r x_c
                FMA_F32X2(v, va.y, Y[p], v);
                FMA_F32X2(v, vb.x, Z[p], v);
                float v0, v1;
                unpack2(v0, v1, v);
                cmlo[p] = fminf(cmlo[p], v0);       // col mins (lane-local)
                cmhi[p] = fminf(cmhi[p], v1);
                pm[p]   = fminf(v0, v1);
            }
            // per-lane row candidate (tree) -> per-warp shared buffer
            sPM[wid][rr][lane] = fminf(fminf(pm[0], pm[1]), fminf(pm[2], pm[3]));
        }
        __syncwarp();
        // transpose-reduce: lane l reduces row (chunk*32 + l) over 32 lane-candidates
        {
            float m = sPM[wid][lane][0];
            #pragma unroll
            for (int j = 1; j < 32; j++) m = fminf(m, sPM[wid][lane][j]);
            rowpart[wid][chunk * CHUNK + lane] = m;
        }
        __syncwarp();
    }

    // ---- col-min partials -> global scratch ----
    float* cm = g_colmin + ((size_t)b * RTILES + tile) * NPTS;
    #pragma unroll
    for (int p = 0; p < CPP; p++) {
        int c0 = 2 * (tid + p * TPB);
        cm[c0]     = cmlo[p];
        cm[c0 + 1] = cmhi[p];
    }

    __syncthreads();

    // ---- row-side finish: merge warp partials, clamp, mask, sum over tile ----
    {
        float mn = rowpart[0][tid];
        #pragma unroll
        for (int w = 1; w < NWARP; w++) mn = fminf(mn, rowpart[w][tid]);
        float wr  = (float)o_w[b * NPTS + row0 + tid];
        float acc = fmaxf(mn, 0.0f) * wr;

        __shared__ float red[NWARP];
        #pragma unroll
        for (int o = 16; o > 0; o >>= 1)
            acc += __shfl_down_sync(0xffffffffu, acc, o);
        if (lane == 0) red[wid] = acc;
        __syncthreads();
        if (tid == 0) {
            float rs = 0.0f;
            #pragma unroll
            for (int w = 0; w < NWARP; w++) rs += red[w];
            g_rowsum[b * RTILES + tile] = rs;
        }
    }

    // ---- decoupled last-block reduction for this batch ----
    __threadfence();
    __syncthreads();
    if (tid == 0) s_last = atomicAdd(&g_ticket[b], 1);
    __syncthreads();
    if (s_last != RTILES - 1) return;

    __threadfence();
    const float* cmb = g_colmin + (size_t)b * RTILES * NPTS;
    float acc = 0.0f;
    #pragma unroll
    for (int k = 0; k < NPTS / TPB; k++) {
        int c = tid + k * TPB;
        float mn = cmb[c];
        #pragma unroll
        for (int t = 1; t < RTILES; t++) mn = fminf(mn, cmb[t * NPTS + c]);
        float wc = (float)t_w[b * NPTS + c];
        acc += fmaxf(mn, 0.0f) * wc;
    }

    __shared__ float red2[NWARP];
    #pragma unroll
    for (int o = 16; o > 0; o >>= 1)
        acc += __shfl_down_sync(0xffffffffu, acc, o);
    if (lane == 0) red2[wid] = acc;
    __syncthreads();
    if (tid == 0) {
        float s = 0.0f;
        #pragma unroll
        for (int w = 0; w < NWARP; w++) s += red2[w];
        float rs = 0.0f;
        #pragma unroll
        for (int t = 0; t < RTILES; t++) rs += g_rowsum[b * RTILES + t];
        out[b] = 0.5f * (rs + s);
        g_ticket[b] = 0;                 // reset for next graph replay
    }
}

extern "C" void kernel_launch(void* const* d_in, const int* in_sizes, int n_in,
                              void* d_out, int out_size) {
    const int*   o_w   = (const int*)  d_in[0];
    const float* o_pts = (const float*)d_in[1];
    const int*   t_w   = (const int*)  d_in[2];
    const float* t_pts = (const float*)d_in[3];
    float* out = (float*)d_out;

    dim3 grid(NB, RTILES);                       // 256 blocks, single launch
    chamfer_kernel<<<grid, TPB>>>(o_w, o_pts, t_w, t_pts, out);
}